// round 1
// baseline (speedup 1.0000x reference)
#include <cuda_runtime.h>
#include <math.h>

#define kA 3
#define kC 20
#define kCH 25   // 5 + C
#define kEPS 1e-7f

// accumulators: obj[0..2], box[3..5], cls[6..8], objcorr[9..11]
__device__ double g_acc[12];

__global__ void k_zero() {
    if (threadIdx.x < 12) g_acc[threadIdx.x] = 0.0;
}

__device__ __forceinline__ float softplusf(float x) {
    // log(1 + e^x), stable
    return fmaxf(x, 0.0f) + log1pf(expf(-fabsf(x)));
}
__device__ __forceinline__ float sigmoidf_(float x) {
    return 1.0f / (1.0f + expf(-x));
}

__device__ float block_reduce_sum(float v) {
    __shared__ float sm[32];
    int tid = threadIdx.x;
#pragma unroll
    for (int o = 16; o > 0; o >>= 1) v += __shfl_down_sync(0xffffffffu, v, o);
    if ((tid & 31) == 0) sm[tid >> 5] = v;
    __syncthreads();
    float r = 0.0f;
    if (tid < 32) {
        int nw = (blockDim.x + 31) >> 5;
        r = (tid < nw) ? sm[tid] : 0.0f;
#pragma unroll
        for (int o = 16; o > 0; o >>= 1) r += __shfl_down_sync(0xffffffffu, r, o);
    }
    __syncthreads();   // protect sm for repeated calls
    return r;          // valid at tid 0
}

// Sum softplus(objectness logit) over all (b, a, h, w) for all 3 scales.
// Reads ONLY channel (a*25+4) planes -> 1/25 of the input bytes.
__global__ void k_obj(const float4* __restrict__ p0,
                      const float4* __restrict__ p1,
                      const float4* __restrict__ p2,
                      int n0, int n1, int n2) {
    int i = blockIdx.x * blockDim.x + threadIdx.x;
    float l0 = 0.f, l1 = 0.f, l2 = 0.f;
    int total = n0 + n1 + n2;
    if (i < total) {
        const float4* p;
        int j, hw4, s;
        if (i < n0)            { p = p0; j = i;            hw4 = 6400 / 4; s = 0; }
        else if (i < n0 + n1)  { p = p1; j = i - n0;       hw4 = 1600 / 4; s = 1; }
        else                   { p = p2; j = i - n0 - n1;  hw4 = 400 / 4;  s = 2; }
        int plane = j / hw4;           // b * kA + a
        int w4    = j - plane * hw4;
        int b = plane / kA;
        int a = plane - b * kA;
        float4 v = p[(size_t)(b * (kA * kCH) + a * kCH + 4) * hw4 + w4];
        float sum = softplusf(v.x) + softplusf(v.y) + softplusf(v.z) + softplusf(v.w);
        if (s == 0) l0 = sum; else if (s == 1) l1 = sum; else l2 = sum;
    }
    float r0 = block_reduce_sum(l0);
    float r1 = block_reduce_sum(l1);
    float r2 = block_reduce_sum(l2);
    if (threadIdx.x == 0) {
        if (r0 != 0.f) atomicAdd(&g_acc[0], (double)r0);
        if (r1 != 0.f) atomicAdd(&g_acc[1], (double)r1);
        if (r2 != 0.f) atomicAdd(&g_acc[2], (double)r2);
    }
}

// One block per scale. Gathers target cells, computes CIoU box loss, class BCE,
// and the objectness correction (-x per anchor at unique target cells).
__global__ void k_targets(const float* __restrict__ p0,
                          const float* __restrict__ p1,
                          const float* __restrict__ p2,
                          const float* __restrict__ tg, int N) {
    int s = blockIdx.x;
    const float* p = (s == 0) ? p0 : (s == 1) ? p1 : p2;
    int W  = (s == 0) ? 80 : (s == 1) ? 40 : 20;
    int HW = W * W;
    float Wf = (float)W;
    __shared__ int keys[1024];
    int tid = threadIdx.x;

    for (int n = tid; n < N && n < 1024; n += blockDim.x) {
        int   b  = (int)tg[n * 6 + 0];
        float cx = tg[n * 6 + 2] * Wf;
        float cy = tg[n * 6 + 3] * Wf;
        int gi = (int)fminf(fmaxf(cx, 0.f), Wf - 1.f);
        int gj = (int)fminf(fmaxf(cy, 0.f), Wf - 1.f);
        keys[n] = b * HW + gj * W + gi;
    }
    __syncthreads();

    float box_l = 0.f, cls_l = 0.f, corr_l = 0.f;

    for (int n = tid; n < N; n += blockDim.x) {
        int   b   = (int)tg[n * 6 + 0];
        int   ci  = (int)tg[n * 6 + 1];
        float tcx = tg[n * 6 + 2], tcy = tg[n * 6 + 3];
        float twn = tg[n * 6 + 4], thn = tg[n * 6 + 5];

        float cx = tcx * Wf, cy = tcy * Wf;
        int gi = (int)fminf(fmaxf(cx, 0.f), Wf - 1.f);
        int gj = (int)fminf(fmaxf(cy, 0.f), Wf - 1.f);
        int key = b * HW + gj * W + gi;

        // dedup: does any earlier target claim the same cell?
        bool unique = true;
        for (int m = 0; m < n; ++m) {
            int km;
            if (m < 1024) km = keys[m];
            else {
                int   bm  = (int)tg[m * 6 + 0];
                float cxm = tg[m * 6 + 2] * Wf;
                float cym = tg[m * 6 + 3] * Wf;
                int gim = (int)fminf(fmaxf(cxm, 0.f), Wf - 1.f);
                int gjm = (int)fminf(fmaxf(cym, 0.f), Wf - 1.f);
                km = bm * HW + gjm * W + gim;
            }
            if (km == key) { unique = false; break; }
        }

        // target box (normalized coords)
        float tx1 = tcx - twn * 0.5f, ty1 = tcy - thn * 0.5f;
        float tx2 = tcx + twn * 0.5f, ty2 = tcy + thn * 0.5f;

        float gif = (float)gi, gjf = (float)gj;
        float twh = (twn * Wf) * 0.5f;   // tw/2 in cell units
        float thh = (thn * Wf) * 0.5f;

        size_t base = (size_t)b * (kA * kCH) * HW + (size_t)(gj * W + gi);

        for (int a = 0; a < kA; ++a) {
            const float* cp = p + base + (size_t)a * kCH * HW;
            float x0 = cp[0];
            float x1 = cp[(size_t)HW];
            float x4 = cp[(size_t)4 * HW];
            float sx = sigmoidf_(x0);
            float sy = sigmoidf_(x1);

            float px1 = (sx + gif - twh) / Wf;
            float py1 = (sy + gjf - thh) / Wf;
            float px2 = (sx + gif + twh) / Wf;
            float py2 = (sy + gjf + thh) / Wf;

            // CIoU (full formula, matching reference incl. eps placement)
            float ix1 = fmaxf(px1, tx1), iy1 = fmaxf(py1, ty1);
            float ix2 = fminf(px2, tx2), iy2 = fminf(py2, ty2);
            float inter = fmaxf(ix2 - ix1, 0.f) * fmaxf(iy2 - iy1, 0.f);
            float ap = (px2 - px1) * (py2 - py1);
            float at = (tx2 - tx1) * (ty2 - ty1);
            float uni = ap + at - inter + kEPS;
            float iou = inter / uni;
            float ex1 = fminf(px1, tx1), ey1 = fminf(py1, ty1);
            float ex2 = fmaxf(px2, tx2), ey2 = fmaxf(py2, ty2);
            float c2 = (ex2 - ex1) * (ex2 - ex1) + (ey2 - ey1) * (ey2 - ey1) + kEPS;
            float dxc = (px1 + px2) * 0.5f - (tx1 + tx2) * 0.5f;
            float dyc = (py1 + py2) * 0.5f - (ty1 + ty2) * 0.5f;
            float rho2 = dxc * dxc + dyc * dyc;
            float pw  = fmaxf(px2 - px1, kEPS), ph  = fmaxf(py2 - py1, kEPS);
            float tww = fmaxf(tx2 - tx1, kEPS), thk = fmaxf(ty2 - ty1, kEPS);
            float dd = atanf(tww / thk) - atanf(pw / ph);
            float v = (4.0f / (float)(M_PI * M_PI)) * dd * dd;
            float alpha = v / (1.0f - iou + v + kEPS);
            float ciou = iou - rho2 / c2 - alpha * v;
            box_l += 1.0f - ciou;

            // class BCE: mean over C of softplus(xc) - [c==ci]*xc
            float csum = 0.f;
#pragma unroll
            for (int c = 0; c < kC; ++c) {
                float xc = cp[(size_t)(5 + c) * HW];
                csum += softplusf(xc);
                if (c == ci) csum -= xc;
            }
            cls_l += csum * (1.0f / (float)kC);

            // objectness correction at unique target cells:
            // BCE(x,1) - BCE(x,0) = -x
            if (unique) corr_l -= x4;
        }
    }

    float rb = block_reduce_sum(box_l);
    float rc = block_reduce_sum(cls_l);
    float ro = block_reduce_sum(corr_l);
    if (tid == 0) {
        g_acc[3 + s] = (double)rb;
        g_acc[6 + s] = (double)rc;
        g_acc[9 + s] = (double)ro;
    }
}

__global__ void k_final(float* __restrict__ out, int N, int c0, int c1, int c2) {
    double lo = (g_acc[0] + g_acc[9])  / (double)c0
              + (g_acc[1] + g_acc[10]) / (double)c1
              + (g_acc[2] + g_acc[11]) / (double)c2;
    int nt = N * kA * 3;
    if (nt < 1) nt = 1;
    double lb = (g_acc[3] + g_acc[4] + g_acc[5]) / (double)nt;
    double lc = (g_acc[6] + g_acc[7] + g_acc[8]) / (double)nt;
    double total = 0.05 * lb + 1.0 * lo + 0.5 * lc;
    out[0] = (float)total;
    out[1] = (float)lb;
    out[2] = (float)lo;
    out[3] = (float)lc;
    out[4] = 0.0f;
}

extern "C" void kernel_launch(void* const* d_in, const int* in_sizes, int n_in,
                              void* d_out, int out_size) {
    const float* p0 = (const float*)d_in[0];
    const float* p1 = (const float*)d_in[1];
    const float* p2 = (const float*)d_in[2];
    const float* tg = (const float*)d_in[3];

    int B = in_sizes[0] / (kA * kCH * 6400);   // 32
    int N = in_sizes[3] / 6;                   // 256

    int n0 = B * kA * (6400 / 4);
    int n1 = B * kA * (1600 / 4);
    int n2 = B * kA * (400 / 4);
    int total = n0 + n1 + n2;

    k_zero<<<1, 32>>>();
    k_obj<<<(total + 255) / 256, 256>>>((const float4*)p0, (const float4*)p1,
                                        (const float4*)p2, n0, n1, n2);
    k_targets<<<3, 256>>>(p0, p1, p2, tg, N);
    k_final<<<1, 1>>>((float*)d_out, N, B * kA * 6400, B * kA * 1600, B * kA * 400);
}

// round 3
// speedup vs baseline: 1.5900x; 1.5900x over previous
#include <cuda_runtime.h>
#include <math.h>

#define kA 3
#define kC 20
#define kCH 25   // 5 + C
#define kEPS 1e-7f
#define kMAXN 1024

// accumulators: obj[0..2], box[3..5], cls[6..8], objcorr[9..11]
__device__ double g_acc[12];
__device__ unsigned int g_cnt;   // zero-init at module load; self-wrapping

__device__ __forceinline__ float softplusf(float x) {
    return fmaxf(x, 0.0f) + log1pf(expf(-fabsf(x)));
}
__device__ __forceinline__ float sigmoidf_(float x) {
    return 1.0f / (1.0f + expf(-x));
}

__device__ float block_reduce_sum(float v) {
    __shared__ float sm[32];
    int tid = threadIdx.x;
#pragma unroll
    for (int o = 16; o > 0; o >>= 1) v += __shfl_down_sync(0xffffffffu, v, o);
    if ((tid & 31) == 0) sm[tid >> 5] = v;
    __syncthreads();
    float r = 0.0f;
    if (tid < 32) {
        int nw = (blockDim.x + 31) >> 5;
        r = (tid < nw) ? sm[tid] : 0.0f;
#pragma unroll
        for (int o = 16; o > 0; o >>= 1) r += __shfl_down_sync(0xffffffffu, r, o);
    }
    __syncthreads();
    return r;   // valid at tid 0
}

// ONE kernel: blocks 0..2 = target gather per scale; blocks 3.. = obj reduction.
// Last block to finish computes the final output and resets accumulators.
__global__ void __launch_bounds__(256)
k_fused(const float* __restrict__ p0,
        const float* __restrict__ p1,
        const float* __restrict__ p2,
        const float* __restrict__ tg,
        float* __restrict__ out,
        int N, int B,
        int n0, int n1, int n2)      // float4 counts per scale for obj
{
    int tid = threadIdx.x;
    int bid = blockIdx.x;

    if (bid >= 3) {
        // ---------------- objectness softplus reduction ----------------
        int nObjBlocks = gridDim.x - 3;
        int i0 = (bid - 3) * blockDim.x + tid;
        int stride = nObjBlocks * blockDim.x;
        float l0 = 0.f, l1 = 0.f, l2 = 0.f;

        // scale 0
        for (int i = i0; i < n0; i += stride) {
            int plane = i / 1600;                 // b*kA + a
            int w4    = i - plane * 1600;
            int b = plane / kA, a = plane - b * kA;
            float4 v = ((const float4*)p0)[(size_t)(b * (kA * kCH) + a * kCH + 4) * 1600 + w4];
            l0 += softplusf(v.x) + softplusf(v.y) + softplusf(v.z) + softplusf(v.w);
        }
        // scale 1
        for (int i = i0; i < n1; i += stride) {
            int plane = i / 400;
            int w4    = i - plane * 400;
            int b = plane / kA, a = plane - b * kA;
            float4 v = ((const float4*)p1)[(size_t)(b * (kA * kCH) + a * kCH + 4) * 400 + w4];
            l1 += softplusf(v.x) + softplusf(v.y) + softplusf(v.z) + softplusf(v.w);
        }
        // scale 2
        for (int i = i0; i < n2; i += stride) {
            int plane = i / 100;
            int w4    = i - plane * 100;
            int b = plane / kA, a = plane - b * kA;
            float4 v = ((const float4*)p2)[(size_t)(b * (kA * kCH) + a * kCH + 4) * 100 + w4];
            l2 += softplusf(v.x) + softplusf(v.y) + softplusf(v.z) + softplusf(v.w);
        }

        float r0 = block_reduce_sum(l0);
        float r1 = block_reduce_sum(l1);
        float r2 = block_reduce_sum(l2);
        if (tid == 0) {
            if (r0 != 0.f) atomicAdd(&g_acc[0], (double)r0);
            if (r1 != 0.f) atomicAdd(&g_acc[1], (double)r1);
            if (r2 != 0.f) atomicAdd(&g_acc[2], (double)r2);
        }
    } else {
        // ---------------- target gather: one block per scale ----------------
        int s = bid;
        const float* p = (s == 0) ? p0 : (s == 1) ? p1 : p2;
        int W  = (s == 0) ? 80 : (s == 1) ? 40 : 20;
        int HW = W * W;
        float Wf = (float)W;

        __shared__ int   keys[kMAXN];
        __shared__ float stg[kMAXN * 6];   // staged targets (N<=1024 assumed; N=256 actual)

        int Nc = (N < kMAXN) ? N : kMAXN;
        for (int i = tid; i < Nc * 6; i += blockDim.x) stg[i] = tg[i];
        __syncthreads();
        for (int n = tid; n < Nc; n += blockDim.x) {
            int   b  = (int)stg[n * 6 + 0];
            float cx = stg[n * 6 + 2] * Wf;
            float cy = stg[n * 6 + 3] * Wf;
            int gi = (int)fminf(fmaxf(cx, 0.f), Wf - 1.f);
            int gj = (int)fminf(fmaxf(cy, 0.f), Wf - 1.f);
            keys[n] = b * HW + gj * W + gi;
        }
        __syncthreads();

        float box_l = 0.f, cls_l = 0.f, corr_l = 0.f;

        int items = Nc * kA;
        for (int it = tid; it < items; it += blockDim.x) {
            int n = it / kA;
            int a = it - n * kA;

            int   b   = (int)stg[n * 6 + 0];
            int   ci  = (int)stg[n * 6 + 1];
            float tcx = stg[n * 6 + 2], tcy = stg[n * 6 + 3];
            float twn = stg[n * 6 + 4], thn = stg[n * 6 + 5];

            float cx = tcx * Wf, cy = tcy * Wf;
            int gi = (int)fminf(fmaxf(cx, 0.f), Wf - 1.f);
            int gj = (int)fminf(fmaxf(cy, 0.f), Wf - 1.f);
            int key = keys[n];

            bool unique = true;
            for (int m = 0; m < n; ++m)
                if (keys[m] == key) { unique = false; break; }

            float tx1 = tcx - twn * 0.5f, ty1 = tcy - thn * 0.5f;
            float tx2 = tcx + twn * 0.5f, ty2 = tcy + thn * 0.5f;
            float gif = (float)gi, gjf = (float)gj;
            float twh = (twn * Wf) * 0.5f;
            float thh = (thn * Wf) * 0.5f;

            const float* cp = p + (size_t)b * (kA * kCH) * HW
                                + (size_t)a * kCH * HW
                                + (size_t)(gj * W + gi);
            float x0 = cp[0];
            float x1 = cp[(size_t)HW];
            float x4 = cp[(size_t)4 * HW];
            float sx = sigmoidf_(x0);
            float sy = sigmoidf_(x1);

            float px1 = (sx + gif - twh) / Wf;
            float py1 = (sy + gjf - thh) / Wf;
            float px2 = (sx + gif + twh) / Wf;
            float py2 = (sy + gjf + thh) / Wf;

            float ix1 = fmaxf(px1, tx1), iy1 = fmaxf(py1, ty1);
            float ix2 = fminf(px2, tx2), iy2 = fminf(py2, ty2);
            float inter = fmaxf(ix2 - ix1, 0.f) * fmaxf(iy2 - iy1, 0.f);
            float ap = (px2 - px1) * (py2 - py1);
            float at = (tx2 - tx1) * (ty2 - ty1);
            float uni = ap + at - inter + kEPS;
            float iou = inter / uni;
            float ex1 = fminf(px1, tx1), ey1 = fminf(py1, ty1);
            float ex2 = fmaxf(px2, tx2), ey2 = fmaxf(py2, ty2);
            float c2 = (ex2 - ex1) * (ex2 - ex1) + (ey2 - ey1) * (ey2 - ey1) + kEPS;
            float dxc = (px1 + px2) * 0.5f - (tx1 + tx2) * 0.5f;
            float dyc = (py1 + py2) * 0.5f - (ty1 + ty2) * 0.5f;
            float rho2 = dxc * dxc + dyc * dyc;
            float pw  = fmaxf(px2 - px1, kEPS), ph  = fmaxf(py2 - py1, kEPS);
            float tww = fmaxf(tx2 - tx1, kEPS), thk = fmaxf(ty2 - ty1, kEPS);
            float dd = atanf(tww / thk) - atanf(pw / ph);
            float v = (4.0f / (float)(M_PI * M_PI)) * dd * dd;
            float alpha = v / (1.0f - iou + v + kEPS);
            float ciou = iou - rho2 / c2 - alpha * v;
            box_l += 1.0f - ciou;

            float csum = 0.f;
#pragma unroll
            for (int c = 0; c < kC; ++c) {
                float xc = cp[(size_t)(5 + c) * HW];
                csum += softplusf(xc);
                if (c == ci) csum -= xc;
            }
            cls_l += csum * (1.0f / (float)kC);

            if (unique) corr_l -= x4;   // BCE(x,1)-BCE(x,0) = -x per anchor
        }

        float rb = block_reduce_sum(box_l);
        float rc = block_reduce_sum(cls_l);
        float ro = block_reduce_sum(corr_l);
        if (tid == 0) {
            atomicAdd(&g_acc[3 + s], (double)rb);
            atomicAdd(&g_acc[6 + s], (double)rc);
            atomicAdd(&g_acc[9 + s], (double)ro);
        }
    }

    // ---------------- last block finalizes + resets ----------------
    __syncthreads();
    __shared__ bool is_last;
    if (tid == 0) {
        __threadfence();
        unsigned int prev = atomicInc(&g_cnt, gridDim.x - 1);  // wraps to 0 on last
        is_last = (prev == gridDim.x - 1);
    }
    __syncthreads();
    if (is_last && tid == 0) {
        __threadfence();
        double acc[12];
#pragma unroll
        for (int i = 0; i < 12; ++i) acc[i] = atomicAdd(&g_acc[i], 0.0);  // coherent read

        double c0 = (double)(B * kA * 6400);
        double c1 = (double)(B * kA * 1600);
        double c2 = (double)(B * kA * 400);
        double lo = (acc[0] + acc[9])  / c0
                  + (acc[1] + acc[10]) / c1
                  + (acc[2] + acc[11]) / c2;
        int nt = N * kA * 3; if (nt < 1) nt = 1;
        double lb = (acc[3] + acc[4] + acc[5]) / (double)nt;
        double lc = (acc[6] + acc[7] + acc[8]) / (double)nt;
        double total = 0.05 * lb + 1.0 * lo + 0.5 * lc;
        out[0] = (float)total;
        out[1] = (float)lb;
        out[2] = (float)lo;
        out[3] = (float)lc;
        out[4] = 0.0f;

        // reset for next graph replay
#pragma unroll
        for (int i = 0; i < 12; ++i) g_acc[i] = 0.0;
        __threadfence();
    }
}

extern "C" void kernel_launch(void* const* d_in, const int* in_sizes, int n_in,
                              void* d_out, int out_size) {
    const float* p0 = (const float*)d_in[0];
    const float* p1 = (const float*)d_in[1];
    const float* p2 = (const float*)d_in[2];
    const float* tg = (const float*)d_in[3];

    int B = in_sizes[0] / (kA * kCH * 6400);   // 32
    int N = in_sizes[3] / 6;                   // 256

    int n0 = B * kA * 1600;   // float4 counts of obj plane per scale
    int n1 = B * kA * 400;
    int n2 = B * kA * 100;
    int total = n0 + n1 + n2;

    int objBlocks = (total + 256 * 4 - 1) / (256 * 4);   // ~4 float4 per thread
    if (objBlocks < 1) objBlocks = 1;
    if (objBlocks > 512) objBlocks = 512;

    k_fused<<<3 + objBlocks, 256>>>(p0, p1, p2, tg, (float*)d_out,
                                    N, B, n0, n1, n2);
}

// round 4
// speedup vs baseline: 1.9896x; 1.2513x over previous
#include <cuda_runtime.h>
#include <math.h>

#define kA 3
#define kC 20
#define kCH 25   // 5 + C
#define kEPS 1e-7f
#define kMAXN 1024
#define kNTB 9   // target blocks: 3 per scale

// accumulators: obj[0..2], box[3..5], cls[6..8], objcorr[9..11]
__device__ double g_acc[12];
__device__ unsigned int g_cnt;   // zero-init; self-wrapping via atomicInc

__device__ __forceinline__ float softplusf(float x) {
    return fmaxf(x, 0.0f) + log1pf(expf(-fabsf(x)));
}
__device__ __forceinline__ float sigmoidf_(float x) {
    return 1.0f / (1.0f + expf(-x));
}

__device__ float block_reduce_sum(float v) {
    __shared__ float sm[32];
    int tid = threadIdx.x;
#pragma unroll
    for (int o = 16; o > 0; o >>= 1) v += __shfl_down_sync(0xffffffffu, v, o);
    if ((tid & 31) == 0) sm[tid >> 5] = v;
    __syncthreads();
    float r = 0.0f;
    if (tid < 32) {
        int nw = (blockDim.x + 31) >> 5;
        r = (tid < nw) ? sm[tid] : 0.0f;
#pragma unroll
        for (int o = 16; o > 0; o >>= 1) r += __shfl_down_sync(0xffffffffu, r, o);
    }
    __syncthreads();
    return r;   // valid at tid 0
}

// Blocks 0..kNTB-1: target gather (3 per scale, 1 item/thread).
// Blocks kNTB..  : obj softplus reduction, 1 float4/thread.
// Last block to finish finalizes output and resets accumulators.
__global__ void __launch_bounds__(256)
k_fused(const float* __restrict__ p0,
        const float* __restrict__ p1,
        const float* __restrict__ p2,
        const float* __restrict__ tg,
        float* __restrict__ out,
        int N, int B,
        int n0, int n1, int n2)      // float4 counts per scale for obj
{
    int tid = threadIdx.x;
    int bid = blockIdx.x;

    if (bid >= kNTB) {
        // ---------------- objectness softplus reduction ----------------
        int nObjBlocks = gridDim.x - kNTB;
        int i0 = (bid - kNTB) * blockDim.x + tid;
        int stride = nObjBlocks * blockDim.x;
        int total = n0 + n1 + n2;
        float l0 = 0.f, l1 = 0.f, l2 = 0.f;
        for (int i = i0; i < total; i += stride) {   // exactly 1 iter when grid sized right
            const float4* p;
            int j, hw4;
            float* acc;
            if (i < n0)            { p = (const float4*)p0; j = i;            hw4 = 1600; acc = &l0; }
            else if (i < n0 + n1)  { p = (const float4*)p1; j = i - n0;       hw4 = 400;  acc = &l1; }
            else                   { p = (const float4*)p2; j = i - n0 - n1;  hw4 = 100;  acc = &l2; }
            int plane = j / hw4;             // b*kA + a
            int w4    = j - plane * hw4;
            int b = plane / kA, a = plane - b * kA;
            float4 v = p[(size_t)(b * (kA * kCH) + a * kCH + 4) * hw4 + w4];
            *acc += softplusf(v.x) + softplusf(v.y) + softplusf(v.z) + softplusf(v.w);
        }
        float r0 = block_reduce_sum(l0);
        float r1 = block_reduce_sum(l1);
        float r2 = block_reduce_sum(l2);
        if (tid == 0) {
            if (r0 != 0.f) atomicAdd(&g_acc[0], (double)r0);
            if (r1 != 0.f) atomicAdd(&g_acc[1], (double)r1);
            if (r2 != 0.f) atomicAdd(&g_acc[2], (double)r2);
        }
    } else {
        // ---------------- target gather: 3 blocks per scale ----------------
        int s     = bid / 3;          // scale
        int slice = bid - s * 3;      // 0..2 slice of items within scale
        const float* p = (s == 0) ? p0 : (s == 1) ? p1 : p2;
        int W  = (s == 0) ? 80 : (s == 1) ? 40 : 20;
        int HW = W * W;
        float Wf = (float)W;

        __shared__ int           keys[kMAXN];
        __shared__ unsigned char uniq[kMAXN];
        __shared__ float         stg[kMAXN * 6];

        int Nc = (N < kMAXN) ? N : kMAXN;
        for (int i = tid; i < Nc * 6; i += blockDim.x) stg[i] = tg[i];
        __syncthreads();
        for (int n = tid; n < Nc; n += blockDim.x) {
            int   b  = (int)stg[n * 6 + 0];
            float cx = stg[n * 6 + 2] * Wf;
            float cy = stg[n * 6 + 3] * Wf;
            int gi = (int)fminf(fmaxf(cx, 0.f), Wf - 1.f);
            int gj = (int)fminf(fmaxf(cy, 0.f), Wf - 1.f);
            keys[n] = b * HW + gj * W + gi;
        }
        __syncthreads();
        // dedup flags, computed once (one n per thread, independent scans)
        for (int n = tid; n < Nc; n += blockDim.x) {
            int key = keys[n];
            unsigned char u = 1;
            for (int m = 0; m < n; ++m)
                if (keys[m] == key) { u = 0; break; }
            uniq[n] = u;
        }
        __syncthreads();

        float box_l = 0.f, cls_l = 0.f, corr_l = 0.f;

        int items = Nc * kA;
        for (int it = slice * blockDim.x + tid; it < items; it += 3 * blockDim.x) {
            int n = it / kA;
            int a = it - n * kA;

            int   b   = (int)stg[n * 6 + 0];
            int   ci  = (int)stg[n * 6 + 1];
            float tcx = stg[n * 6 + 2], tcy = stg[n * 6 + 3];
            float twn = stg[n * 6 + 4], thn = stg[n * 6 + 5];

            float cx = tcx * Wf, cy = tcy * Wf;
            int gi = (int)fminf(fmaxf(cx, 0.f), Wf - 1.f);
            int gj = (int)fminf(fmaxf(cy, 0.f), Wf - 1.f);

            float tx1 = tcx - twn * 0.5f, ty1 = tcy - thn * 0.5f;
            float tx2 = tcx + twn * 0.5f, ty2 = tcy + thn * 0.5f;
            float gif = (float)gi, gjf = (float)gj;
            float twh = (twn * Wf) * 0.5f;
            float thh = (thn * Wf) * 0.5f;

            const float* cp = p + (size_t)b * (kA * kCH) * HW
                                + (size_t)a * kCH * HW
                                + (size_t)(gj * W + gi);
            float x0 = cp[0];
            float x1 = cp[(size_t)HW];
            float x4 = cp[(size_t)4 * HW];
            float sx = sigmoidf_(x0);
            float sy = sigmoidf_(x1);

            float px1 = (sx + gif - twh) / Wf;
            float py1 = (sy + gjf - thh) / Wf;
            float px2 = (sx + gif + twh) / Wf;
            float py2 = (sy + gjf + thh) / Wf;

            float ix1 = fmaxf(px1, tx1), iy1 = fmaxf(py1, ty1);
            float ix2 = fminf(px2, tx2), iy2 = fminf(py2, ty2);
            float inter = fmaxf(ix2 - ix1, 0.f) * fmaxf(iy2 - iy1, 0.f);
            float ap = (px2 - px1) * (py2 - py1);
            float at = (tx2 - tx1) * (ty2 - ty1);
            float uni = ap + at - inter + kEPS;
            float iou = inter / uni;
            float ex1 = fminf(px1, tx1), ey1 = fminf(py1, ty1);
            float ex2 = fmaxf(px2, tx2), ey2 = fmaxf(py2, ty2);
            float c2 = (ex2 - ex1) * (ex2 - ex1) + (ey2 - ey1) * (ey2 - ey1) + kEPS;
            float dxc = (px1 + px2) * 0.5f - (tx1 + tx2) * 0.5f;
            float dyc = (py1 + py2) * 0.5f - (ty1 + ty2) * 0.5f;
            float rho2 = dxc * dxc + dyc * dyc;
            float pw  = fmaxf(px2 - px1, kEPS), ph  = fmaxf(py2 - py1, kEPS);
            float tww = fmaxf(tx2 - tx1, kEPS), thk = fmaxf(ty2 - ty1, kEPS);
            float dd = atanf(tww / thk) - atanf(pw / ph);
            float v = (4.0f / (float)(M_PI * M_PI)) * dd * dd;
            float alpha = v / (1.0f - iou + v + kEPS);
            float ciou = iou - rho2 / c2 - alpha * v;
            box_l += 1.0f - ciou;

            float csum = 0.f;
#pragma unroll
            for (int c = 0; c < kC; ++c) {
                float xc = cp[(size_t)(5 + c) * HW];
                csum += softplusf(xc);
                if (c == ci) csum -= xc;
            }
            cls_l += csum * (1.0f / (float)kC);

            if (uniq[n]) corr_l -= x4;   // BCE(x,1)-BCE(x,0) = -x per anchor
        }

        float rb = block_reduce_sum(box_l);
        float rc = block_reduce_sum(cls_l);
        float ro = block_reduce_sum(corr_l);
        if (tid == 0) {
            if (rb != 0.f) atomicAdd(&g_acc[3 + s], (double)rb);
            if (rc != 0.f) atomicAdd(&g_acc[6 + s], (double)rc);
            if (ro != 0.f) atomicAdd(&g_acc[9 + s], (double)ro);
        }
    }

    // ---------------- last block finalizes + resets ----------------
    __syncthreads();
    __shared__ bool is_last;
    if (tid == 0) {
        __threadfence();
        unsigned int prev = atomicInc(&g_cnt, gridDim.x - 1);  // wraps to 0 on last
        is_last = (prev == gridDim.x - 1);
    }
    __syncthreads();
    if (is_last && tid == 0) {
        __threadfence();
        double acc[12];
#pragma unroll
        for (int i = 0; i < 12; ++i) acc[i] = atomicAdd(&g_acc[i], 0.0);  // coherent read

        double c0 = (double)(B * kA * 6400);
        double c1 = (double)(B * kA * 1600);
        double c2 = (double)(B * kA * 400);
        double lo = (acc[0] + acc[9])  / c0
                  + (acc[1] + acc[10]) / c1
                  + (acc[2] + acc[11]) / c2;
        int nt = N * kA * 3; if (nt < 1) nt = 1;
        double lb = (acc[3] + acc[4] + acc[5]) / (double)nt;
        double lc = (acc[6] + acc[7] + acc[8]) / (double)nt;
        double total = 0.05 * lb + 1.0 * lo + 0.5 * lc;
        out[0] = (float)total;
        out[1] = (float)lb;
        out[2] = (float)lo;
        out[3] = (float)lc;
        out[4] = 0.0f;

        // reset for next graph replay
#pragma unroll
        for (int i = 0; i < 12; ++i) g_acc[i] = 0.0;
        __threadfence();
    }
}

extern "C" void kernel_launch(void* const* d_in, const int* in_sizes, int n_in,
                              void* d_out, int out_size) {
    const float* p0 = (const float*)d_in[0];
    const float* p1 = (const float*)d_in[1];
    const float* p2 = (const float*)d_in[2];
    const float* tg = (const float*)d_in[3];

    int B = in_sizes[0] / (kA * kCH * 6400);   // 32
    int N = in_sizes[3] / 6;                   // 256

    int n0 = B * kA * 1600;   // float4 counts of obj plane per scale
    int n1 = B * kA * 400;
    int n2 = B * kA * 100;
    int total = n0 + n1 + n2;  // 201600

    int objBlocks = (total + 255) / 256;       // 1 float4 per thread
    if (objBlocks < 1) objBlocks = 1;
    if (objBlocks > 4096) objBlocks = 4096;

    k_fused<<<kNTB + objBlocks, 256>>>(p0, p1, p2, tg, (float*)d_out,
                                       N, B, n0, n1, n2);
}